// round 2
// baseline (speedup 1.0000x reference)
#include <cuda_runtime.h>
#include <math.h>

#define BB   64
#define LQV  20
#define LDV  512
#define DV   300
#define EQV  5
#define EDV  10
#define DESCV 20
#define KCV  10

// ---------------- constants ----------------
__constant__ float c_MU[11]  = {1.0f,0.9f,0.7f,0.5f,0.3f,0.1f,-0.1f,-0.3f,-0.5f,-0.7f,-0.9f};
__constant__ float c_IS2[11] = {500000.0f,50.f,50.f,50.f,50.f,50.f,50.f,50.f,50.f,50.f,50.f};
// pool order from reference: (qtype, dtype), types: 0=uni 1=bi 2=tri 3=ent
__constant__ int c_poolQ[16] = {0,0,0,1,2,1,1,2,2,3,3,3,0,1,2,3};
__constant__ int c_poolD[16] = {0,2,1,0,0,1,2,1,2,0,1,2,3,3,3,3};

// ---------------- scratch (device globals; no allocations allowed) --------
__device__ float g_Wt_word[6*300*128];   // transposed word conv slices [slice][k][n]
__device__ float g_Wt_desc[5*300*128];   // transposed desc conv slices
__device__ float g_Yq[BB*LQV*768];
__device__ float g_Yd[(size_t)BB*LDV*768];
__device__ float g_Ydesc[(size_t)19200*640];   // 6400 q-rows then 12800 d-rows
__device__ float g_qu[BB*20*128];
__device__ float g_qb[BB*19*128];
__device__ float g_qt[BB*18*128];
__device__ float g_du[(size_t)BB*512*128];
__device__ float g_db[(size_t)BB*511*128];
__device__ float g_dt[(size_t)BB*510*128];
__device__ float g_qs[BB*5*128];
__device__ float g_ds[BB*10*128];
__device__ float g_sump[2*BB*4*300];     // partial embedding sums
__device__ float g_bow[2*BB*128];        // [0..63]=q bow, [64..127]=d bow
__device__ float g_feats[BB*176];

// ---------------- helpers ----------------
__device__ __forceinline__ float block_sum_128(float v) {
    __shared__ float sh[4];
    v += __shfl_down_sync(0xffffffffu, v, 16);
    v += __shfl_down_sync(0xffffffffu, v, 8);
    v += __shfl_down_sync(0xffffffffu, v, 4);
    v += __shfl_down_sync(0xffffffffu, v, 2);
    v += __shfl_down_sync(0xffffffffu, v, 1);
    if ((threadIdx.x & 31) == 0) sh[threadIdx.x >> 5] = v;
    __syncthreads();
    float r = sh[0] + sh[1] + sh[2] + sh[3];
    __syncthreads();
    return r;
}

// ---------------- weight transpose ----------------
__global__ void k_prep_weights(const float* uW, const float* bW, const float* tW, const float* dW) {
    int stride = gridDim.x * blockDim.x;
    for (int e = blockIdx.x*blockDim.x + threadIdx.x; e < 6*300*128; e += stride) {
        int s = e / (300*128); int r = e % (300*128); int k = r >> 7; int n = r & 127;
        float v;
        if (s == 0)      v = uW[n*300 + k];
        else if (s <= 2) v = bW[n*600 + (s-1)*300 + k];
        else             v = tW[n*900 + (s-3)*300 + k];
        g_Wt_word[e] = v;
    }
    for (int e = blockIdx.x*blockDim.x + threadIdx.x; e < 5*300*128; e += stride) {
        int i = e / (300*128); int r = e % (300*128); int k = r >> 7; int n = r & 127;
        g_Wt_desc[e] = dW[n*1500 + i*300 + k];
    }
}

// ---------------- partial embedding sums (for bow) ----------------
__global__ void k_sum_part(const int* qwt, const int* dwt, const float* emb) {
    int dim = threadIdx.x; if (dim >= 300) return;
    int b = blockIdx.x; int isD = blockIdx.y; int sl = blockIdx.z;
    const int* tok; int L;
    if (isD) { tok = dwt + b*LDV; L = LDV; } else { tok = qwt + b*LQV; L = LQV; }
    int per = (L + 3) >> 2;
    int l0 = sl * per; int l1 = min(L, l0 + per);
    float s0 = 0.f, s1 = 0.f, s2 = 0.f, s3 = 0.f;
    int l = l0;
    for (; l + 4 <= l1; l += 4) {
        s0 += emb[(size_t)tok[l  ]*300 + dim];
        s1 += emb[(size_t)tok[l+1]*300 + dim];
        s2 += emb[(size_t)tok[l+2]*300 + dim];
        s3 += emb[(size_t)tok[l+3]*300 + dim];
    }
    for (; l < l1; l++) s0 += emb[(size_t)tok[l]*300 + dim];
    g_sump[(((isD*BB) + b)*4 + sl)*300 + dim] = s0 + s1 + s2 + s3;
}

// ---------------- bow projection ----------------
__global__ void k_bow(const float* bow_W, const float* bow_b) {
    int b = blockIdx.x, isD = blockIdx.y, o = threadIdx.x;
    __shared__ float s[300];
    const float* base = g_sump + ((size_t)(isD*BB) + b)*4*300;
    for (int i = o; i < 300; i += 128)
        s[i] = base[i] + base[300+i] + base[600+i] + base[900+i];
    __syncthreads();
    float acc = 0.f;
    const float* w = bow_W + o*300;
    #pragma unroll 4
    for (int k = 0; k < 300; k++) acc = fmaf(s[k], w[k], acc);
    int L = isD ? LDV : LQV;
    g_bow[(isD*BB + b)*128 + o] = acc + (float)L * bow_b[o];
}

// ---------------- gathered GEMM: Y[m, s*128+n] = emb[tok[m]] . Wt[s][:,n] ----
// WHICH: 0 = query words (Yq, 6 slices, ld 768)
//        1 = doc words   (Yd, 6 slices, ld 768)
//        2 = query desc  (Ydesc rows [0,6400),   5 slices, ld 640)
//        3 = doc desc    (Ydesc rows [6400,19200), 5 slices, ld 640)
template<int WHICH>
__global__ void __launch_bounds__(256) k_gemm(const int* tokens, const float* emb) {
    const float* Wt_base = (WHICH <= 1) ? g_Wt_word : g_Wt_desc;
    float* Y;
    int ldY;
    if      (WHICH == 0) { Y = g_Yq;   ldY = 768; }
    else if (WHICH == 1) { Y = g_Yd;   ldY = 768; }
    else if (WHICH == 2) { Y = g_Ydesc; ldY = 640; }
    else                 { Y = g_Ydesc + (size_t)BB*EQV*DESCV*640; ldY = 640; }

    int s = blockIdx.y;
    const float* Wt = Wt_base + (size_t)s*300*128;
    int m0 = blockIdx.x * 64;
    __shared__ float As[20][68];
    __shared__ float Bs[20][128];
    __shared__ int   toks[64];
    int t = threadIdx.x;
    if (t < 64) toks[t] = tokens[m0 + t];
    __syncthreads();

    float c[8][4];
    #pragma unroll
    for (int r = 0; r < 8; r++) { c[r][0]=0.f; c[r][1]=0.f; c[r][2]=0.f; c[r][3]=0.f; }

    int tc = t & 31, tr = t >> 5;
    int r0 = tr * 8, c0 = tc * 4;
    int arow = t >> 2;
    int aks  = (t & 3) * 5;
    const float* abase = emb + (size_t)toks[arow]*300 + aks;

    for (int k0 = 0; k0 < 300; k0 += 20) {
        #pragma unroll
        for (int j = 0; j < 5; j++) As[aks + j][arow] = abase[k0 + j];
        #pragma unroll
        for (int i = 0; i < 10; i++) {
            int e = t + i*256; int kk = e >> 7, nn = e & 127;
            Bs[kk][nn] = Wt[(size_t)(k0 + kk)*128 + nn];
        }
        __syncthreads();
        #pragma unroll
        for (int kk = 0; kk < 20; kk++) {
            float4 a0 = *(const float4*)&As[kk][r0];
            float4 a1 = *(const float4*)&As[kk][r0 + 4];
            float4 b4 = *(const float4*)&Bs[kk][c0];
            float av[8] = {a0.x,a0.y,a0.z,a0.w,a1.x,a1.y,a1.z,a1.w};
            #pragma unroll
            for (int r = 0; r < 8; r++) {
                c[r][0] = fmaf(av[r], b4.x, c[r][0]);
                c[r][1] = fmaf(av[r], b4.y, c[r][1]);
                c[r][2] = fmaf(av[r], b4.z, c[r][2]);
                c[r][3] = fmaf(av[r], b4.w, c[r][3]);
            }
        }
        __syncthreads();
    }
    #pragma unroll
    for (int r = 0; r < 8; r++) {
        float4* dst = (float4*)&Y[(size_t)(m0 + r0 + r)*ldY + s*128 + c0];
        *dst = make_float4(c[r][0], c[r][1], c[r][2], c[r][3]);
    }
}

// ---------------- combine conv slices + relu + l2 normalize ----------------
// ISD: 0 = query (L=20, out g_qu/g_qb/g_qt), 1 = doc (L=512, out g_du/g_db/g_dt)
template<int ISD>
__global__ void k_combine(const float* ub, const float* bbias, const float* tb) {
    const float* Y = ISD ? g_Yd : g_Yq;
    float* outU = ISD ? g_du : g_qu;
    float* outB = ISD ? g_db : g_qb;
    float* outT = ISD ? g_dt : g_qt;
    const int L = ISD ? LDV : LQV;

    int idx = blockIdx.x;
    int l = idx % L;
    int o = threadIdx.x;
    const float* y0 = Y + (size_t)idx * 768;
    float u = fmaxf(y0[o] + ub[o], 0.f);
    bool hasB = (l < L-1), hasT = (l < L-2);
    float bv = 0.f, tv = 0.f;
    if (hasB) bv = fmaxf(y0[128+o] + y0[768+256+o] + bbias[o], 0.f);
    if (hasT) tv = fmaxf(y0[384+o] + y0[768+512+o] + y0[1536+640+o] + tb[o], 0.f);
    float su = block_sum_128(u*u);
    float sb = block_sum_128(bv*bv);
    float st = block_sum_128(tv*tv);
    int b = idx / L;
    outU[(size_t)idx*128 + o] = u / fmaxf(sqrtf(su), 1e-10f);
    if (hasB) outB[((size_t)b*(L-1) + l)*128 + o] = bv / fmaxf(sqrtf(sb), 1e-10f);
    if (hasT) outT[((size_t)b*(L-2) + l)*128 + o] = tv / fmaxf(sqrtf(st), 1e-10f);
}

// ---------------- entity branch ----------------
__global__ void k_ent(const int* qei, const int* qew, const int* dei, const int* dew,
                      const float* ent_emb, const float* car_emb, const float* des_b) {
    int x = blockIdx.x;            // 0..959 : first 320 q entities, then 640 d entities
    bool isQ = x < BB*EQV;
    int o = threadIdx.x;           // 128
    int b, e, rowbase, eid;
    const int* carIds; const float* bow;
    if (isQ) {
        b = x / EQV; e = x % EQV;
        rowbase = x * DESCV;
        carIds = qew + b*EQV*KCV + e*KCV;
        eid = qei[b*EQV + e];
        bow = g_bow + (size_t)b*128;
    } else {
        int xi = x - BB*EQV;
        b = xi / EDV; e = xi % EDV;
        rowbase = BB*EQV*DESCV + xi*DESCV;
        carIds = dew + b*EDV*KCV + e*KCV;
        eid = dei[b*EDV + e];
        bow = g_bow + (size_t)(BB + b)*128;
    }
    // desc conv + max pool (relu >= 0 so init 0 is the identity for max-of-relu)
    float bias = des_b[o];
    float mx = 0.f;
    for (int pos = 0; pos < 16; pos++) {
        float sacc = bias;
        #pragma unroll
        for (int i = 0; i < 5; i++)
            sacc += g_Ydesc[(size_t)(rowbase + pos + i)*640 + i*128 + o];
        mx = fmaxf(mx, sacc);
    }
    __shared__ float bs[128];
    __shared__ float tS[10][128];
    __shared__ float sc[10];
    __shared__ float att[10];
    bs[o] = bow[o];
    __syncthreads();
    for (int k = 0; k < 10; k++) {
        float v = car_emb[(size_t)carIds[k]*128 + o];
        tS[k][o] = v;
        float p = block_sum_128(bs[o] * v);
        if (o == 0) sc[k] = p;
    }
    __syncthreads();
    if (o == 0) {
        float m = sc[0];
        #pragma unroll
        for (int k = 1; k < 10; k++) m = fmaxf(m, sc[k]);
        float sum = 0.f;
        #pragma unroll
        for (int k = 0; k < 10; k++) { att[k] = expf(sc[k] - m); sum += att[k]; }
        float inv = 1.f / sum;
        #pragma unroll
        for (int k = 0; k < 10; k++) att[k] *= inv;
    }
    __syncthreads();
    float ew = 0.f;
    #pragma unroll
    for (int k = 0; k < 10; k++) ew = fmaf(att[k], tS[k][o], ew);
    float val = ent_emb[(size_t)eid*128 + o] + mx + ew;
    float nsq = block_sum_128(val * val);
    float nv = val / fmaxf(sqrtf(nsq), 1e-10f);
    if (isQ) g_qs[(size_t)(b*EQV + e)*128 + o] = nv;
    else     g_ds[(size_t)(b*EDV + e)*128 + o] = nv;
}

// ---------------- kernel pooling (one block per (batch, pool)) -------------
__global__ void __launch_bounds__(256) k_pool(const float* qwm, const float* qem,
                                              const float* dwm, const float* dem) {
    int blk = blockIdx.x;
    int b = blk >> 4, p = blk & 15;
    int qt = c_poolQ[p], dt = c_poolD[p];

    const float* Q; int Lq; const float* mqp;
    switch (qt) {
        case 0: Q = g_qu + (size_t)b*20*128; Lq = 20; mqp = qwm + b*LQV; break;
        case 1: Q = g_qb + (size_t)b*19*128; Lq = 19; mqp = qwm + b*LQV; break;
        case 2: Q = g_qt + (size_t)b*18*128; Lq = 18; mqp = qwm + b*LQV; break;
        default:Q = g_qs + (size_t)b*5*128;  Lq = 5;  mqp = qem + b*EQV; break;
    }
    const float* Dp; int Ld; const float* mdp;
    switch (dt) {
        case 0: Dp = g_du + (size_t)b*512*128; Ld = 512; mdp = dwm + b*LDV; break;
        case 1: Dp = g_db + (size_t)b*511*128; Ld = 511; mdp = dwm + b*LDV; break;
        case 2: Dp = g_dt + (size_t)b*510*128; Ld = 510; mdp = dwm + b*LDV; break;
        default:Dp = g_ds + (size_t)b*10*128;  Ld = 10;  mdp = dem + b*EDV; break;
    }

    __shared__ float Qs[20][132];
    __shared__ float DtS[128][36];
    __shared__ float simS[20][36];
    __shared__ float mdS[32];
    __shared__ float lpsS[20*11];

    int t = threadIdx.x;
    for (int e = t; e < Lq*128; e += 256) { int q = e >> 7, k = e & 127; Qs[q][k] = Q[e]; }

    int myq = t / 11, myk = t % 11;
    bool active = t < Lq * 11;
    float mu_ = c_MU[myk], is2 = c_IS2[myk];
    float acc = 0.f;

    for (int cc0 = 0; cc0 < Ld; cc0 += 32) {
        int cn = min(32, Ld - cc0);
        __syncthreads();                          // prev phase-B done before Dt reload
        for (int e = t; e < cn*128; e += 256) {
            int cc = e >> 7, k = e & 127;
            DtS[k][cc] = Dp[(size_t)(cc0 + cc)*128 + k];
        }
        if (t < cn) mdS[t] = mdp[cc0 + t];
        __syncthreads();
        int ncg = (cn + 3) >> 2;
        for (int mt = t; mt < Lq*8; mt += 256) {
            int q = mt >> 3, cg = mt & 7;
            if (cg < ncg) {
                float s0 = 0.f, s1 = 0.f, s2 = 0.f, s3 = 0.f;
                const float* qrow = &Qs[q][0];
                #pragma unroll 4
                for (int kk = 0; kk < 128; kk++) {
                    float qa = qrow[kk];
                    float4 d4 = *(const float4*)&DtS[kk][cg << 2];
                    s0 = fmaf(qa, d4.x, s0);
                    s1 = fmaf(qa, d4.y, s1);
                    s2 = fmaf(qa, d4.z, s2);
                    s3 = fmaf(qa, d4.w, s3);
                }
                int cb = cg << 2;
                simS[q][cb] = s0; simS[q][cb+1] = s1; simS[q][cb+2] = s2; simS[q][cb+3] = s3;
            }
        }
        __syncthreads();
        if (active) {
            const float* srow = &simS[myq][0];
            for (int cc = 0; cc < cn; cc++) {
                float df = srow[cc] - mu_;
                acc = fmaf(mdS[cc], expf(-df*df*is2), acc);
            }
        }
    }
    __syncthreads();
    if (active)
        lpsS[myq*11 + myk] = logf(fmaxf(acc, 1e-10f)) * 0.01f * mqp[myq];
    __syncthreads();
    if (t < 11) {
        float s = 0.f;
        for (int q = 0; q < Lq; q++) s += lpsS[q*11 + t];
        g_feats[b*176 + p*11 + t] = s;
    }
}

// ---------------- final dense + tanh ----------------
__global__ void k_final(const float* W, const float* b0, float* out) {
    int b = threadIdx.x;
    if (b < BB) {
        float s = b0[0];
        #pragma unroll 4
        for (int j = 0; j < 176; j++) s = fmaf(g_feats[b*176 + j], W[j], s);
        out[b] = tanhf(s);
    }
}

// ---------------- launch ----------------
extern "C" void kernel_launch(void* const* d_in, const int* in_sizes, int n_in,
                              void* d_out, int out_size) {
    const int*   qwt  = (const int*)  d_in[0];
    const float* qwm  = (const float*)d_in[1];
    const int*   qei  = (const int*)  d_in[2];
    const int*   qet  = (const int*)  d_in[3];
    const int*   qew  = (const int*)  d_in[4];
    const float* qem  = (const float*)d_in[5];
    const int*   dwt  = (const int*)  d_in[6];
    const float* dwm  = (const float*)d_in[7];
    const int*   dei  = (const int*)  d_in[8];
    const int*   det  = (const int*)  d_in[9];
    const int*   dew  = (const int*)  d_in[10];
    const float* dem  = (const float*)d_in[11];
    const float* wrd  = (const float*)d_in[12];
    const float* ente = (const float*)d_in[13];
    const float* care = (const float*)d_in[14];
    const float* bowW = (const float*)d_in[15];
    const float* bowb = (const float*)d_in[16];
    const float* uW   = (const float*)d_in[17];
    const float* ub   = (const float*)d_in[18];
    const float* bW   = (const float*)d_in[19];
    const float* bb   = (const float*)d_in[20];
    const float* tW   = (const float*)d_in[21];
    const float* tb   = (const float*)d_in[22];
    const float* dW   = (const float*)d_in[23];
    const float* db_  = (const float*)d_in[24];
    const float* fW   = (const float*)d_in[25];
    const float* fb   = (const float*)d_in[26];
    float* out = (float*)d_out;

    k_prep_weights<<<240, 256>>>(uW, bW, tW, dW);
    k_sum_part<<<dim3(BB, 2, 4), 320>>>(qwt, dwt, wrd);
    k_bow<<<dim3(BB, 2), 128>>>(bowW, bowb);

    k_gemm<0><<<dim3(BB*LQV/64, 6), 256>>>(qwt, wrd);
    k_gemm<1><<<dim3(BB*LDV/64, 6), 256>>>(dwt, wrd);
    k_gemm<2><<<dim3(BB*EQV*DESCV/64, 5), 256>>>(qet, wrd);
    k_gemm<3><<<dim3(BB*EDV*DESCV/64, 5), 256>>>(det, wrd);

    k_combine<0><<<BB*LQV, 128>>>(ub, bb, tb);
    k_combine<1><<<BB*LDV, 128>>>(ub, bb, tb);

    k_ent<<<BB*(EQV + EDV), 128>>>(qei, qew, dei, dew, ente, care, db_);
    k_pool<<<BB*16, 256>>>(qwm, qem, dwm, dem);
    k_final<<<1, 64>>>(fW, fb, out);
}